// round 9
// baseline (speedup 1.0000x reference)
#include <cuda_runtime.h>

#define FULL 0xffffffffu

// fast ssim loss term: 1 - (2 m_x m_y + c1)/(m_x^2 + m_y^2 + c1)
__device__ __forceinline__ float ssim_term(float mx, float my) {
    const float c1 = 0.2f;
    return 1.0f - __fdividef(2.0f * mx * my + c1,
                             mx * mx + my * my + c1);
}

__device__ __forceinline__ unsigned smem_u32(const void* p) {
    unsigned a;
    asm("{ .reg .u64 t; cvta.to.shared.u64 t, %1; cvt.u32.u64 %0, t; }"
        : "=r"(a) : "l"(p));
    return a;
}
__device__ __forceinline__ unsigned mapa_rank0(unsigned addr) {
    unsigned r;
    asm("mapa.shared::cluster.u32 %0, %1, 0;" : "=r"(r) : "r"(addr));
    return r;
}
__device__ __forceinline__ void st_cluster_f32(unsigned addr, float v) {
    asm volatile("st.shared::cluster.f32 [%0], %1;" :: "r"(addr), "f"(v)
                 : "memory");
}

// 16 CTAs = ONE cluster (4x4 grid of 64x64 tiles), 256 threads each.
// Thread owns a 4x4 pixel block (one d=6 node), 8 x LDG.128 up front.
// Cross-CTA fan-in: DSMEM stores into rank 0 + ONE mbarrier arrival per CTA
// (count=16). No cluster barrier, no atomics, no membar.gpu. Warps 1-7 of
// every CTA retire immediately after the CTA-local __syncthreads.
// Depth weights W_d = 0.25^d * K_LOSS[d]:
//   d=8: 1/65536  d=7: 2/16384  d=6: 3/4096  d=5: 4/1024  d=4: 5/256
//   d=3: 6/64     d=2: 7/16     d=1: 2       d=0: 9
__global__ __launch_bounds__(256, 1) __cluster_dims__(16, 1, 1)
void loss_quadtree_kernel(const float* __restrict__ x,
                          const float* __restrict__ y,
                          float* __restrict__ out) {
    __shared__ float n8x[64];   // d=5 node sums (8x8 grid per CTA)
    __shared__ float n8y[64];
    __shared__ float accW[8];   // per-warp loss partials
    __shared__ float pSx[16];   // rank 0 only: per-tile sums (DSMEM targets)
    __shared__ float pSy[16];
    __shared__ float pL[16];    // rank 0 only: per-CTA loss partials
    __shared__ __align__(8) unsigned long long mbar;  // rank 0 only

    const int t    = threadIdx.x;
    const int lane = t & 31;
    const int w    = t >> 5;
    const int bid  = blockIdx.x;                   // == cluster rank
    const int tx   = bid & 3, ty = bid >> 2;       // tile in 4x4 grid
    const int qx   = lane & 15;                    // block col (0..15)
    const int qy   = 2 * w + (lane >> 4);          // block row (0..15)
    const int r    = ty * 64 + qy * 4;
    const int c    = tx * 64 + qx * 4;

    // Rank 0 inits the fan-in mbarrier immediately. Remote arrivals happen
    // only after a full DRAM load + tree (>=~800 cycles into each CTA), and
    // cluster CTAs are co-scheduled in one wave, so init wins the race.
    if (bid == 0 && t == 0) {
        unsigned a = smem_u32(&mbar);
        asm volatile("mbarrier.init.shared.b64 [%0], %1;"
                     :: "r"(a), "r"(16u) : "memory");
        asm volatile("fence.mbarrier_init.release.cluster;" ::: "memory");
    }

    // 8 x LDG.128 issued up front (MLP=8)
    const float4* x4 = (const float4*)x;
    const float4* y4 = (const float4*)y;
    const int base = r * 64 + (c >> 2);            // row stride = 256/4
    float4 xr0 = x4[base],        xr1 = x4[base + 64];
    float4 xr2 = x4[base + 128],  xr3 = x4[base + 192];
    float4 yr0 = y4[base],        yr1 = y4[base + 64];
    float4 yr2 = y4[base + 128],  yr3 = y4[base + 192];

    // d=8: 16 per-pixel terms
    float s8 =
        ssim_term(xr0.x, yr0.x) + ssim_term(xr0.y, yr0.y) +
        ssim_term(xr0.z, yr0.z) + ssim_term(xr0.w, yr0.w) +
        ssim_term(xr1.x, yr1.x) + ssim_term(xr1.y, yr1.y) +
        ssim_term(xr1.z, yr1.z) + ssim_term(xr1.w, yr1.w) +
        ssim_term(xr2.x, yr2.x) + ssim_term(xr2.y, yr2.y) +
        ssim_term(xr2.z, yr2.z) + ssim_term(xr2.w, yr2.w) +
        ssim_term(xr3.x, yr3.x) + ssim_term(xr3.y, yr3.y) +
        ssim_term(xr3.z, yr3.z) + ssim_term(xr3.w, yr3.w);
    float acc = (1.0f / 65536.0f) * s8;

    // d=7: 4 quad (2x2) sums
    float qxa = xr0.x + xr0.y + xr1.x + xr1.y;
    float qxb = xr0.z + xr0.w + xr1.z + xr1.w;
    float qxc = xr2.x + xr2.y + xr3.x + xr3.y;
    float qxd = xr2.z + xr2.w + xr3.z + xr3.w;
    float qya = yr0.x + yr0.y + yr1.x + yr1.y;
    float qyb = yr0.z + yr0.w + yr1.z + yr1.w;
    float qyc = yr2.x + yr2.y + yr3.x + yr3.y;
    float qyd = yr2.z + yr2.w + yr3.z + yr3.w;
    acc += (2.0f / 16384.0f) *
           (ssim_term(qxa * 0.5f, qya * 0.5f) +
            ssim_term(qxb * 0.5f, qyb * 0.5f) +
            ssim_term(qxc * 0.5f, qyc * 0.5f) +
            ssim_term(qxd * 0.5f, qyd * 0.5f));

    // d=6: this thread's full 4x4 block
    float S4x = qxa + qxb + qxc + qxd;
    float S4y = qya + qyb + qyc + qyd;
    acc += (3.0f / 4096.0f) * ssim_term(S4x * 0.25f, S4y * 0.25f);

    // d=5 via shuffles: rows 2w/2w+1 (lane +16), then col pair (lane +1)
    float ax = S4x + __shfl_down_sync(FULL, S4x, 16);
    float ay = S4y + __shfl_down_sync(FULL, S4y, 16);
    float S8x = ax + __shfl_down_sync(FULL, ax, 1);
    float S8y = ay + __shfl_down_sync(FULL, ay, 1);
    if (lane < 16 && !(lane & 1)) {
        acc += (4.0f / 1024.0f) * ssim_term(S8x * 0.125f, S8y * 0.125f);
        n8x[w * 8 + (lane >> 1)] = S8x;
        n8y[w * 8 + (lane >> 1)] = S8y;
    }

    // per-warp loss reduction (deterministic xor butterfly)
    #pragma unroll
    for (int o = 16; o > 0; o >>= 1) acc += __shfl_xor_sync(FULL, acc, o);
    if (lane == 0) accW[w] = acc;

    __syncthreads();              // only CTA-wide barrier
    if (w != 0) return;           // warps 1..7 of ALL CTAs retire here

    // ---- warp 0: d=4..2 from the 8x8 d=5 node grid ----
    float acc2 = 0.0f, S16x = 0.0f, S16y = 0.0f;
    if (lane < 16) {
        int ny = lane >> 2, nx = lane & 3;       // 4x4 d=4 node grid
        int b = ny * 16 + nx * 2;
        S16x = n8x[b] + n8x[b + 1] + n8x[b + 8] + n8x[b + 9];
        S16y = n8y[b] + n8y[b + 1] + n8y[b + 8] + n8y[b + 9];
        acc2 = (5.0f / 256.0f) *
               ssim_term(S16x * (1.0f / 16.0f), S16y * (1.0f / 16.0f));
    }
    if (lane < 8) acc2 += accW[lane];

    // d=3: lanes {0,2,8,10}
    float bx = S16x + __shfl_down_sync(FULL, S16x, 1);
    float by = S16y + __shfl_down_sync(FULL, S16y, 1);
    float S32x = bx + __shfl_down_sync(FULL, bx, 4);
    float S32y = by + __shfl_down_sync(FULL, by, 4);
    if (lane == 0 || lane == 2 || lane == 8 || lane == 10)
        acc2 += (6.0f / 64.0f) *
                ssim_term(S32x * (1.0f / 32.0f), S32y * (1.0f / 32.0f));

    // d=2: one node per CTA (tile total), lane 0
    float cx = S32x + __shfl_down_sync(FULL, S32x, 2);
    float cy = S32y + __shfl_down_sync(FULL, S32y, 2);
    float S64x = cx + __shfl_down_sync(FULL, cx, 8);
    float S64y = cy + __shfl_down_sync(FULL, cy, 8);
    if (lane == 0)
        acc2 += (7.0f / 16.0f) *
                ssim_term(S64x * (1.0f / 64.0f), S64y * (1.0f / 64.0f));

    #pragma unroll
    for (int o = 16; o > 0; o >>= 1) acc2 += __shfl_xor_sync(FULL, acc2, o);

    // lane 0: publish into rank 0's smem, then ONE release-arrival per CTA
    if (lane == 0) {
        st_cluster_f32(mapa_rank0(smem_u32(&pL[bid])),  acc2);
        st_cluster_f32(mapa_rank0(smem_u32(&pSx[bid])), S64x);
        st_cluster_f32(mapa_rank0(smem_u32(&pSy[bid])), S64y);
        unsigned rb = mapa_rank0(smem_u32(&mbar));
        asm volatile(
            "mbarrier.arrive.release.cluster.shared::cluster.b64 _, [%0];"
            :: "r"(rb) : "memory");
    }
    if (bid != 0) return;         // non-rank0 warp 0 retires

    // ---- finisher: rank 0, warp 0 — wait for all 16 arrivals ----
    {
        unsigned a = smem_u32(&mbar);
        asm volatile(
            "{\n\t"
            ".reg .pred P;\n"
            "W%=:\n\t"
            "mbarrier.try_wait.parity.acquire.cluster.shared::cta.b64 P, [%0], 0;\n\t"
            "@!P bra W%=;\n\t"
            "}"
            :: "r"(a) : "memory");
    }

    float ftot = (lane < 16) ? pL[lane] : 0.0f;

    // d=1: 4 nodes (h=128), lanes 0..3, from local smem
    float S128x = 0.0f, S128y = 0.0f;
    if (lane < 4) {
        int ny = lane >> 1, nx = lane & 1;
        int b = ny * 8 + nx * 2;                 // (2ny)*4 + 2nx in 4x4 grid
        S128x = pSx[b] + pSx[b + 1] + pSx[b + 4] + pSx[b + 5];
        S128y = pSy[b] + pSy[b + 1] + pSy[b + 4] + pSy[b + 5];
        ftot += 2.0f *
                ssim_term(S128x * (1.0f / 128.0f), S128y * (1.0f / 128.0f));
    }

    // d=0: root
    float ex = S128x + __shfl_down_sync(FULL, S128x, 1);
    float ey = S128y + __shfl_down_sync(FULL, S128y, 1);
    float S256x = ex + __shfl_down_sync(FULL, ex, 2);
    float S256y = ey + __shfl_down_sync(FULL, ey, 2);
    if (lane == 0)
        ftot += 9.0f *
                ssim_term(S256x * (1.0f / 256.0f), S256y * (1.0f / 256.0f));

    #pragma unroll
    for (int o = 16; o > 0; o >>= 1) ftot += __shfl_xor_sync(FULL, ftot, o);

    if (lane == 0) out[0] = ftot;
}

extern "C" void kernel_launch(void* const* d_in, const int* in_sizes, int n_in,
                              void* d_out, int out_size) {
    const float* x = (const float*)d_in[0];   // input  (256x256 f32)
    const float* y = (const float*)d_in[1];   // target (256x256 f32)
    float* out = (float*)d_out;               // scalar f32

    // 16-CTA cluster exceeds the portable limit (8); opt in. Host-side,
    // idempotent, capture-safe (not a stream operation).
    cudaFuncSetAttribute(loss_quadtree_kernel,
                         cudaFuncAttributeNonPortableClusterSizeAllowed, 1);
    loss_quadtree_kernel<<<16, 256>>>(x, y, out);
}